// round 17
// baseline (speedup 1.0000x reference)
#include <cuda_runtime.h>
#include <cuda_bf16.h>
#include <cstdint>
#include <cstdio>

// Problem constants
#define BB   32
#define LLEN 36864
#define CCH  16
#define DDIM 512
#define KW   24
#define LOUT 1536               // LLEN / KW
#define MM   (BB * LOUT)        // 49152 rows
#define KD   384                // CCH * KW reduction dim
#define NOFF 48                 // 2*KW offset channels

// -------- scratch (device globals: allocation-guard safe) --------
__device__ __align__(128) __nv_bfloat16 g_WoffH[NOFF * KD];          // [o][kc] hi
__device__ __align__(128) __nv_bfloat16 g_WoffL[NOFF * KD];          // [o][kc] lo
__device__ __align__(128) float g_OFF[(size_t)MM * NOFF];            // [m][o]
__device__ __align__(128) __nv_bfloat16 g_Ah[(size_t)MM * KD];       // hi split [m][kc]
__device__ __align__(128) __nv_bfloat16 g_Al[(size_t)MM * KD];       // lo split [m][kc]
__device__ __align__(128) __nv_bfloat16 g_Wh[(size_t)DDIM * KD];     // [d][kc]
__device__ __align__(128) __nv_bfloat16 g_Wl[(size_t)DDIM * KD];     // [d][kc]

// ---------------- helpers ----------------
__device__ __forceinline__ uint32_t smem_u32(const void* p) {
    uint32_t a;
    asm("{ .reg .u64 t; cvta.to.shared.u64 t, %1; cvt.u32.u64 %0, t; }" : "=r"(a) : "l"(p));
    return a;
}

#define LDSM_X4(r, addr)                                                         \
    asm volatile("ldmatrix.sync.aligned.m8n8.x4.shared.b16 {%0,%1,%2,%3}, [%4];" \
                 : "=r"((r)[0]), "=r"((r)[1]), "=r"((r)[2]), "=r"((r)[3])        \
                 : "r"(addr))

#define MMA_BF16(c, a, b0, b1)                                                  \
    asm volatile("mma.sync.aligned.m16n8k16.row.col.f32.bf16.bf16.f32 "         \
                 "{%0,%1,%2,%3}, {%4,%5,%6,%7}, {%8,%9}, {%0,%1,%2,%3};"        \
                 : "+f"((c)[0]), "+f"((c)[1]), "+f"((c)[2]), "+f"((c)[3])       \
                 : "r"((a)[0]), "r"((a)[1]), "r"((a)[2]), "r"((a)[3]),          \
                   "r"(b0), "r"(b1))

#define CP_ASYNC16(dst, src) \
    asm volatile("cp.async.cg.shared.global [%0], [%1], 16;" :: "r"(dst), "l"(src))
#define CP_COMMIT() asm volatile("cp.async.commit_group;" ::: "memory")
#define CP_WAIT(n)  asm volatile("cp.async.wait_group %0;" :: "n"(n) : "memory")
#define PREFETCH_L2(addr) \
    asm volatile("prefetch.global.L2 [%0];" :: "l"(addr))

#define STS_V4(addr, a, b, c, d)                                   \
    asm volatile("st.shared.v4.b32 [%0], {%1, %2, %3, %4};"        \
                 :: "r"(addr), "r"(a), "r"(b), "r"(c), "r"(d) : "memory")

// swizzled byte offset inside a [rows][32] bf16 tile (rows of 64B = 4 x 16B chunks)
__device__ __forceinline__ uint32_t g2_swz(int row, int chunk) {
    return (uint32_t)(row * 64 + ((chunk ^ ((row >> 1) & 3)) << 4));
}

__device__ __forceinline__ uint32_t pack_hi2(float a, float b, uint32_t& lo) {
    __nv_bfloat16 h0 = __float2bfloat16(a), h1 = __float2bfloat16(b);
    __nv_bfloat16 l0 = __float2bfloat16(a - __bfloat162float(h0));
    __nv_bfloat16 l1 = __float2bfloat16(b - __bfloat162float(h1));
    lo = (uint32_t)__bfloat16_as_ushort(l0) | ((uint32_t)__bfloat16_as_ushort(l1) << 16);
    return (uint32_t)__bfloat16_as_ushort(h0) | ((uint32_t)__bfloat16_as_ushort(h1) << 16);
}

// -------- kernel 0: permute + split weights --------
__global__ void permute_weights_kernel(const float* __restrict__ w_off,
                                       const float* __restrict__ w_def) {
    int t = blockIdx.x * blockDim.x + threadIdx.x;
    if (t < KD * DDIM) {
        int d = t / KD, kc = t % KD;
        int k = kc >> 4, c = kc & 15;
        float v = w_def[(size_t)d * KD + c * KW + k];
        __nv_bfloat16 h = __float2bfloat16(v);
        __nv_bfloat16 l = __float2bfloat16(v - __bfloat162float(h));
        g_Wh[t] = h;
        g_Wl[t] = l;
    }
    if (t < NOFF * KD) {
        int o = t / KD, kc = t % KD;
        int k = kc >> 4, c = kc & 15;
        float v = w_off[(size_t)o * KD + c * KW + k];
        __nv_bfloat16 h = __float2bfloat16(v);
        __nv_bfloat16 l = __float2bfloat16(v - __bfloat162float(h));
        g_WoffH[t] = h;
        g_WoffL[t] = l;
    }
}

// -------- offset conv on tensor cores: x[M,384] @ WoffT[384,48] + b_off -> g_OFF --------
#define OC_BK      32
#define OC_NCH     (KD / OC_BK)                 // 12
#define OC_AT_B    (128 * OC_BK * 2)            // 8192 per A split tile
#define OC_WT_B    (NOFF * OC_BK * 2)           // 3072 per W split tile
#define OC_STAGE_B (2 * OC_AT_B + 2 * OC_WT_B)  // 22528
#define OC_SMEM    (3 * OC_STAGE_B)             // 67584

__global__ void __launch_bounds__(256, 2)
offconv_mma(const float* __restrict__ x, const float* __restrict__ b_off,
            float* __restrict__ offout)
{
    extern __shared__ __align__(1024) char smem[];
    const uint32_t sbase = smem_u32(smem);

    const int tid  = threadIdx.x;
    const int wid  = tid >> 5;
    const int lane = tid & 31;
    const int row0 = blockIdx.x * 128;

    const int p_row  = tid >> 1;
    const int p_half = tid & 1;
    const float* xrow = x + (size_t)(row0 + p_row) * KD + p_half * 16;

    uint32_t vh[8], vl[8];
    auto gather_a = [&](int t) {
        const float4* src = (const float4*)(xrow + t * OC_BK);
        #pragma unroll
        for (int q = 0; q < 4; ++q) {
            float4 v = src[q];
            vh[q * 2 + 0] = pack_hi2(v.x, v.y, vl[q * 2 + 0]);
            vh[q * 2 + 1] = pack_hi2(v.z, v.w, vl[q * 2 + 1]);
        }
    };
    auto sts_a = [&](int t) {
        const uint32_t sb = sbase + (t % 3) * OC_STAGE_B;
        const uint32_t o0 = g2_swz(p_row, p_half * 2);
        const uint32_t o1 = g2_swz(p_row, p_half * 2 + 1);
        STS_V4(sb + o0, vh[0], vh[1], vh[2], vh[3]);
        STS_V4(sb + o1, vh[4], vh[5], vh[6], vh[7]);
        STS_V4(sb + OC_AT_B + o0, vl[0], vl[1], vl[2], vl[3]);
        STS_V4(sb + OC_AT_B + o1, vl[4], vl[5], vl[6], vl[7]);
    };
    auto cpw = [&](int t) {
        const int kt = t * OC_BK;
        const uint32_t sb = sbase + (t % 3) * OC_STAGE_B + 2 * OC_AT_B;
        #pragma unroll
        for (int i = 0; i < 2; ++i) {
            int id = i * 256 + tid;
            if (id < 2 * (OC_WT_B / 16)) {
                int sp  = id / (OC_WT_B / 16);
                int j   = id % (OC_WT_B / 16);
                int row = j >> 2;
                int c   = j & 3;
                const __nv_bfloat16* src =
                    (sp ? g_WoffL : g_WoffH) + (size_t)row * KD + kt + c * 8;
                CP_ASYNC16(sb + sp * OC_WT_B + g2_swz(row, c), src);
            }
        }
    };

    float acc[6][4];
    #pragma unroll
    for (int nf = 0; nf < 6; ++nf)
        #pragma unroll
        for (int q = 0; q < 4; ++q) acc[nf][q] = 0.f;

    const int a_row = wid * 16 + (lane & 15);
    const int a_chb = lane >> 4;
    const int b_row = (lane & 7) + ((lane >> 4) << 3);
    const int b_chb = (lane >> 3) & 1;

    gather_a(0); sts_a(0); cpw(0); CP_COMMIT();
    gather_a(1); sts_a(1); cpw(1); CP_COMMIT();
    gather_a(2);

    #pragma unroll 1
    for (int t = 0; t < OC_NCH; ++t) {
        CP_WAIT(1);
        __syncthreads();
        if (t + 2 < OC_NCH) { sts_a(t + 2); cpw(t + 2); }
        CP_COMMIT();

        const uint32_t sb = sbase + (t % 3) * OC_STAGE_B;
        #pragma unroll
        for (int ks = 0; ks < 2; ++ks) {
            uint32_t afh[4], afl[4];
            uint32_t oa = g2_swz(a_row, 2 * ks + a_chb);
            LDSM_X4(afh, sb + oa);
            LDSM_X4(afl, sb + OC_AT_B + oa);
            #pragma unroll
            for (int nf4 = 0; nf4 < 3; ++nf4) {
                uint32_t bfr[4];
                LDSM_X4(bfr, sb + 2 * OC_AT_B + g2_swz(b_row + nf4 * 16, 2 * ks + b_chb));
                #pragma unroll
                for (int p = 0; p < 2; ++p) {
                    const int nf = 2 * nf4 + p;
                    MMA_BF16(acc[nf], afh, bfr[2 * p], bfr[2 * p + 1]);
                    MMA_BF16(acc[nf], afl, bfr[2 * p], bfr[2 * p + 1]);
                }
            }
            #pragma unroll
            for (int nf4 = 0; nf4 < 3; ++nf4) {
                uint32_t bfr[4];
                LDSM_X4(bfr, sb + 2 * OC_AT_B + OC_WT_B + g2_swz(b_row + nf4 * 16, 2 * ks + b_chb));
                #pragma unroll
                for (int p = 0; p < 2; ++p) {
                    const int nf = 2 * nf4 + p;
                    MMA_BF16(acc[nf], afh, bfr[2 * p], bfr[2 * p + 1]);
                }
            }
        }
        if (t + 3 < OC_NCH) gather_a(t + 3);
    }

    const int r = row0 + wid * 16 + (lane >> 2);
    #pragma unroll
    for (int nf = 0; nf < 6; ++nf) {
        const int o = nf * 8 + (lane & 3) * 2;
        float2 b2 = *(const float2*)&b_off[o];
        float2 v0, v1;
        v0.x = acc[nf][0] + b2.x;
        v0.y = acc[nf][1] + b2.y;
        v1.x = acc[nf][2] + b2.x;
        v1.y = acc[nf][3] + b2.y;
        *(float2*)&offout[(size_t)r * NOFF + o]       = v0;
        *(float2*)&offout[(size_t)(r + 8) * NOFF + o] = v1;
    }
}

// -------- sampler: one thread per (m, tap); full lane utilization --------
// blocks of 192 threads = 8 rows x 24 taps
__global__ void __launch_bounds__(192)
sampler_kernel(const float* __restrict__ x) {
    const int tid = threadIdx.x;
    const int m   = blockIdx.x * 8 + tid / KW;
    const int k   = tid % KW;
    const int b   = m / LOUT;
    const int wo  = m - b * LOUT;

    float2 d2 = ((const float2*)(g_OFF + (size_t)m * NOFF))[k]; // (dy, dx)
    float dy = d2.x, dx = d2.y;

    float wy = fmaxf(0.f, 1.f - fabsf(dy));
    float px = (float)(wo * KW + k) + dx;
    bool valid = (px > -1.f) && (px < (float)LLEN);
    float x0f = floorf(px);
    float lw  = px - x0f;
    int i0 = (int)x0f;
    int i1 = i0 + 1;
    float w0 = (valid && i0 >= 0 && i0 < LLEN) ? (1.f - lw) * wy : 0.f;
    float w1 = (valid && i1 >= 0 && i1 < LLEN) ? lw * wy : 0.f;
    int i0c = min(max(i0, 0), LLEN - 1);
    int i1c = min(max(i1, 0), LLEN - 1);

    const float4* p0 = (const float4*)(x + ((size_t)b * LLEN + i0c) * CCH);
    const float4* p1 = (const float4*)(x + ((size_t)b * LLEN + i1c) * CCH);

    uint32_t wh[8], wl[8];
    #pragma unroll
    for (int q = 0; q < 4; ++q) {
        float4 v0 = p0[q], v1 = p1[q];
        float r0 = w0 * v0.x + w1 * v1.x;
        float r1 = w0 * v0.y + w1 * v1.y;
        float r2 = w0 * v0.z + w1 * v1.z;
        float r3 = w0 * v0.w + w1 * v1.w;
        wh[q * 2 + 0] = pack_hi2(r0, r1, wl[q * 2 + 0]);
        wh[q * 2 + 1] = pack_hi2(r2, r3, wl[q * 2 + 1]);
    }
    uint4* ph = (uint4*)(g_Ah + (size_t)m * KD + k * CCH);
    uint4* pl = (uint4*)(g_Al + (size_t)m * KD + k * CCH);
    ph[0] = make_uint4(wh[0], wh[1], wh[2], wh[3]);
    ph[1] = make_uint4(wh[4], wh[5], wh[6], wh[7]);
    pl[0] = make_uint4(wl[0], wl[1], wl[2], wl[3]);
    pl[1] = make_uint4(wl[4], wl[5], wl[6], wl[7]);
}

// -------- main projection: mma.sync bf16-split GEMM + L2 prefetch --------
// CTA tile 128x128, BK=32 bf16, 3-stage cp.async pipeline (96KB, 2 CTAs/SM),
// plus prefetch.global.L2 two chunks ahead of the cp.async stage (4 ahead of compute).
#define G2_BK      32
#define G2_NCH     (KD / G2_BK)             // 12
#define G2_STAGES  3
#define G2_TILE_B  (128 * G2_BK * 2)        // 8192 B per matrix tile
#define G2_STAGE_B (4 * G2_TILE_B)          // 32768 B (Ah, Al, Wh, Wl)
#define G2_SMEM    (G2_STAGES * G2_STAGE_B) // 98304 B

__global__ void __launch_bounds__(256, 2)
gemm2_mma(const __nv_bfloat16* __restrict__ Ah, const __nv_bfloat16* __restrict__ Al,
          const __nv_bfloat16* __restrict__ Wh, const __nv_bfloat16* __restrict__ Wl,
          const float* __restrict__ bias, float* __restrict__ out)
{
    extern __shared__ __align__(1024) char smem[];
    const uint32_t sbase = smem_u32(smem);

    const int tid    = threadIdx.x;
    const int wid    = tid >> 5;
    const int lane   = tid & 31;
    const int warp_m = wid & 3;
    const int warp_n = wid >> 2;
    const int row0   = blockIdx.y * 128;
    const int col0   = blockIdx.x * 128;

    const __nv_bfloat16* srcs[4] = {
        Ah + (size_t)row0 * KD, Al + (size_t)row0 * KD,
        Wh + (size_t)col0 * KD, Wl + (size_t)col0 * KD };

    auto load_stage = [&](int t) {
        const int kt = t * G2_BK;
        const uint32_t sb = sbase + (t % G2_STAGES) * G2_STAGE_B;
        #pragma unroll
        for (int i = 0; i < 8; ++i) {
            int id  = i * 256 + tid;
            int mat = id >> 9;            // 512 chunks per tile
            int j   = id & 511;
            int row = j >> 2;
            int c   = j & 3;
            const __nv_bfloat16* src = srcs[mat] + (size_t)row * KD + kt + c * 8;
            CP_ASYNC16(sb + mat * G2_TILE_B + g2_swz(row, c), src);
        }
        // L2 prefetch two chunks ahead of this stage (one 128B-aligned line per (mat,row))
        const int pf = t + 2;
        if (pf < G2_NCH) {
            const int kpf = pf * G2_BK;
            #pragma unroll
            for (int i = 0; i < 8; ++i) {
                int id = i * 256 + tid;
                if ((id & 3) == 0) {      // c == 0: one per (mat,row)
                    int mat = id >> 9;
                    int row = (id & 511) >> 2;
                    const char* base = (const char*)(srcs[mat] + (size_t)row * KD + kpf);
                    PREFETCH_L2((const void*)((uintptr_t)base & ~(uintptr_t)127));
                }
            }
        }
    };

    float acc[2][8][4];
    #pragma unroll
    for (int mf = 0; mf < 2; ++mf)
        #pragma unroll
        for (int nf = 0; nf < 8; ++nf)
            #pragma unroll
            for (int q = 0; q < 4; ++q) acc[mf][nf][q] = 0.f;

    const int a_row = warp_m * 32 + (lane & 15);     // + mf*16
    const int a_chb = (lane >> 4);                   // + 2*ks
    const int b_row = warp_n * 64 + (lane & 7) + ((lane >> 4) << 3);  // + nf4*16
    const int b_chb = ((lane >> 3) & 1);             // + 2*ks

    load_stage(0); CP_COMMIT();
    load_stage(1); CP_COMMIT();

    #pragma unroll 1
    for (int t = 0; t < G2_NCH; ++t) {
        CP_WAIT(1);                 // stage t resident (only t+1 may be pending)
        __syncthreads();            // all reads of stage (t-1) are done
        if (t + 2 < G2_NCH) load_stage(t + 2);
        CP_COMMIT();

        const uint32_t sb = sbase + (t % G2_STAGES) * G2_STAGE_B;
        #pragma unroll
        for (int ks = 0; ks < 2; ++ks) {
            uint32_t afh[2][4], afl[2][4];
            #pragma unroll
            for (int mf = 0; mf < 2; ++mf) {
                uint32_t o = g2_swz(a_row + mf * 16, 2 * ks + a_chb);
                LDSM_X4(afh[mf], sb + 0 * G2_TILE_B + o);
                LDSM_X4(afl[mf], sb + 1 * G2_TILE_B + o);
            }
            #pragma unroll
            for (int nf4 = 0; nf4 < 4; ++nf4) {
                uint32_t bfr[4];
                LDSM_X4(bfr, sb + 2 * G2_TILE_B + g2_swz(b_row + nf4 * 16, 2 * ks + b_chb));
                #pragma unroll
                for (int p = 0; p < 2; ++p) {
                    const int nf = 2 * nf4 + p;
                    #pragma unroll
                    for (int mf = 0; mf < 2; ++mf) {
                        MMA_BF16(acc[mf][nf], afh[mf], bfr[2 * p], bfr[2 * p + 1]);
                        MMA_BF16(acc[mf][nf], afl[mf], bfr[2 * p], bfr[2 * p + 1]);
                    }
                }
            }
            #pragma unroll
            for (int nf4 = 0; nf4 < 4; ++nf4) {
                uint32_t bfr[4];
                LDSM_X4(bfr, sb + 3 * G2_TILE_B + g2_swz(b_row + nf4 * 16, 2 * ks + b_chb));
                #pragma unroll
                for (int p = 0; p < 2; ++p) {
                    const int nf = 2 * nf4 + p;
                    #pragma unroll
                    for (int mf = 0; mf < 2; ++mf)
                        MMA_BF16(acc[mf][nf], afh[mf], bfr[2 * p], bfr[2 * p + 1]);
                }
            }
        }
    }

    #pragma unroll
    for (int mf = 0; mf < 2; ++mf) {
        const int r = row0 + warp_m * 32 + mf * 16 + (lane >> 2);
        #pragma unroll
        for (int nf = 0; nf < 8; ++nf) {
            const int n = col0 + warp_n * 64 + nf * 8 + (lane & 3) * 2;
            float2 b2 = *(const float2*)&bias[n];
            float2 v0, v1;
            v0.x = acc[mf][nf][0] + b2.x;
            v0.y = acc[mf][nf][1] + b2.y;
            v1.x = acc[mf][nf][2] + b2.x;
            v1.y = acc[mf][nf][3] + b2.y;
            *(float2*)&out[(size_t)r * DDIM + n]       = v0;
            *(float2*)&out[(size_t)(r + 8) * DDIM + n] = v1;
        }
    }
}

extern "C" void kernel_launch(void* const* d_in, const int* in_sizes, int n_in,
                              void* d_out, int out_size) {
    (void)in_sizes; (void)n_in; (void)out_size;
    const float* x     = (const float*)d_in[0];
    const float* w_off = (const float*)d_in[1];
    const float* b_off = (const float*)d_in[2];
    const float* w_def = (const float*)d_in[3];
    const float* b_def = (const float*)d_in[4];
    float* out = (float*)d_out;

    void* p;
    cudaGetSymbolAddress(&p, g_OFF);   float* off   = (float*)p;
    cudaGetSymbolAddress(&p, g_Ah);    __nv_bfloat16* ah = (__nv_bfloat16*)p;
    cudaGetSymbolAddress(&p, g_Al);    __nv_bfloat16* al = (__nv_bfloat16*)p;
    cudaGetSymbolAddress(&p, g_Wh);    __nv_bfloat16* wh = (__nv_bfloat16*)p;
    cudaGetSymbolAddress(&p, g_Wl);    __nv_bfloat16* wl = (__nv_bfloat16*)p;

    cudaFuncSetAttribute(gemm2_mma, cudaFuncAttributeMaxDynamicSharedMemorySize, G2_SMEM);
    cudaFuncSetAttribute(offconv_mma, cudaFuncAttributeMaxDynamicSharedMemorySize, OC_SMEM);

    // 0) permute/split weights (both W_def and W_off)
    permute_weights_kernel<<<(KD * DDIM + 255) / 256, 256>>>(w_off, w_def);

    // 1) offset conv on tensor cores: x [M,384] @ WoffT [384,48] + b_off -> g_OFF
    offconv_mma<<<MM / 128, 256, OC_SMEM>>>(x, b_off, off);

    // 2) deformable bilinear sampling -> bf16 hi/lo [M,384]
    sampler_kernel<<<MM / 8, 192>>>(x);

    // 3) main projection on tensor cores: (Ah+Al) @ (Wh+Wl)^T + b_def -> out
    gemm2_mma<<<dim3(DDIM / 128, MM / 128), 256, G2_SMEM>>>(ah, al, wh, wl, b_def, out);
}